// round 1
// baseline (speedup 1.0000x reference)
#include <cuda_runtime.h>
#include <cstdint>

#define BB   16
#define CIN  64
#define COUT 64
#define NN   1024
#define LL   12
#define CL   768   // COUT*LL

// scratch (device globals: allocation-free)
__device__ float g_xt[(size_t)BB * NN * CL];   // [b][n][c*12+l]  (GEMM B-operand)
__device__ float g_A [(size_t)BB * NN * NN];   // softmax result pre-swap [b][i][j]
__device__ float g_f [(size_t)BB * NN];

// ------------------------------------------------------------------
// Kernel 1: conv0 (1x3, pad 1 on L) + bias, writes Xt layout, computes f
// block = (b, 16 consecutive n). 256 thr = 16 cout-groups(4) x 16 n
// ------------------------------------------------------------------
#define NT 16
#define WPITCH 65
#define PPITCH 897   // 64*14 + 1

__global__ __launch_bounds__(256) void conv_kernel(
    const float* __restrict__ in, const float* __restrict__ w0,
    const float* __restrict__ b0, const float* __restrict__ w1)
{
    extern __shared__ float sm[];
    float* Wsh = sm;                    // [192][WPITCH] as [cin*3+kt][cout]
    float* Psh = sm + 192 * WPITCH;     // [NT][PPITCH] : [nt][cin*14 + x]
    float* red = Psh + NT * PPITCH;     // [NT][16]

    int blk = blockIdx.x;
    int b   = blk >> 6;                 // 64 n-tiles per batch
    int n0  = (blk & 63) * NT;
    int tid = threadIdx.x;

    // weights transposed into smem
    for (int idx = tid; idx < COUT * 192; idx += 256) {
        int cout = idx / 192, r = idx % 192;
        Wsh[r * WPITCH + cout] = w0[idx];
    }
    // zero L-padding slots (x=0 and x=13)
    for (int idx = tid; idx < NT * CIN * 2; idx += 256) {
        int nt = idx >> 7; int r = idx & 127; int cin = r >> 1; int side = r & 1;
        Psh[nt * PPITCH + cin * 14 + side * 13] = 0.f;
    }
    // input patches: in[b, cin, n0+nt, l]
    const float* inb = in + (size_t)b * CIN * NN * LL;
    for (int idx = tid; idx < NT * CIN * LL; idx += 256) {
        int cin = idx / (NT * LL); int r = idx % (NT * LL);
        int nt = r / LL; int l = r % LL;
        Psh[nt * PPITCH + cin * 14 + l + 1] = inb[((size_t)cin * NN + n0 + nt) * LL + l];
    }
    __syncthreads();

    int cg = tid >> 4, nt = tid & 15;
    float acc[4][12];
    #pragma unroll
    for (int u = 0; u < 4; u++) {
        float bv = b0[cg * 4 + u];
        #pragma unroll
        for (int l = 0; l < 12; l++) acc[u][l] = bv;
    }
    const float* prow = Psh + nt * PPITCH;
    for (int cin = 0; cin < CIN; cin++) {
        float pv[14];
        #pragma unroll
        for (int x = 0; x < 14; x++) pv[x] = prow[cin * 14 + x];
        #pragma unroll
        for (int kt = 0; kt < 3; kt++) {
            float wv[4];
            #pragma unroll
            for (int u = 0; u < 4; u++) wv[u] = Wsh[(cin * 3 + kt) * WPITCH + cg * 4 + u];
            #pragma unroll
            for (int u = 0; u < 4; u++)
                #pragma unroll
                for (int l = 0; l < 12; l++)
                    acc[u][l] += wv[u] * pv[l + kt];
        }
    }
    // write Xt and accumulate f-partial
    float* xt = g_xt + ((size_t)(b * NN + n0 + nt)) * CL;
    float fp = 0.f;
    #pragma unroll
    for (int u = 0; u < 4; u++) {
        int c = cg * 4 + u;
        #pragma unroll
        for (int l = 0; l < 12; l++) {
            xt[c * 12 + l] = acc[u][l];
            fp += acc[u][l] * __ldg(&w1[c * 12 + l]);
        }
    }
    red[nt * 16 + cg] = fp;
    __syncthreads();
    if (cg == 0) {
        float s = 0.f;
        #pragma unroll
        for (int k = 0; k < 16; k++) s += red[nt * 16 + k];
        g_f[b * NN + n0 + nt] = s;
    }
}

// ------------------------------------------------------------------
// Kernel 2: per-row softmax of leakyrelu(f_i + f_j) + adj  -> g_A
// one 256-thread block per (b, i) row
// ------------------------------------------------------------------
__global__ __launch_bounds__(256) void softmax_kernel(const float* __restrict__ adj)
{
    int row = blockIdx.x;        // b*1024 + i
    int b = row >> 10;
    int tid = threadIdx.x;
    const float* arow = adj + (size_t)row * NN;
    const float* fb = g_f + b * NN;
    float fi = fb[row & 1023];

    float zv[4]; float mx = -1e30f;
    #pragma unroll
    for (int k = 0; k < 4; k++) {
        int j = tid + k * 256;
        float lg = fi + fb[j];
        float z = (lg >= 0.f ? lg : 0.2f * lg) + arow[j];
        zv[k] = z; mx = fmaxf(mx, z);
    }
    __shared__ float sred[32];
    #pragma unroll
    for (int o = 16; o > 0; o >>= 1) mx = fmaxf(mx, __shfl_xor_sync(0xffffffffu, mx, o));
    if ((tid & 31) == 0) sred[tid >> 5] = mx;
    __syncthreads();
    if (tid < 32) {
        float v = (tid < 8) ? sred[tid] : -1e30f;
        #pragma unroll
        for (int o = 4; o > 0; o >>= 1) v = fmaxf(v, __shfl_xor_sync(0xffffffffu, v, o));
        if (tid == 0) sred[0] = v;
    }
    __syncthreads();
    mx = sred[0];
    __syncthreads();

    float ev[4]; float s = 0.f;
    #pragma unroll
    for (int k = 0; k < 4; k++) { ev[k] = __expf(zv[k] - mx); s += ev[k]; }
    #pragma unroll
    for (int o = 16; o > 0; o >>= 1) s += __shfl_xor_sync(0xffffffffu, s, o);
    if ((tid & 31) == 0) sred[tid >> 5] = s;
    __syncthreads();
    if (tid < 32) {
        float v = (tid < 8) ? sred[tid] : 0.f;
        #pragma unroll
        for (int o = 4; o > 0; o >>= 1) v += __shfl_xor_sync(0xffffffffu, v, o);
        if (tid == 0) sred[0] = v;
    }
    __syncthreads();
    float inv = 1.f / sred[0];

    float* Ar = g_A + (size_t)row * NN;
    #pragma unroll
    for (int k = 0; k < 4; k++) Ar[tid + k * 256] = ev[k] * inv;
}

// ------------------------------------------------------------------
// Kernel 3: attention output = A^T per batch (32x32 smem tiles)
// ------------------------------------------------------------------
__global__ void transpose_kernel(float* __restrict__ outAtt)
{
    __shared__ float tile[32][33];
    int b = blockIdx.z;
    const float* Ab = g_A + (size_t)b * NN * NN;
    float* ob = outAtt + (size_t)b * NN * NN;
    int x = blockIdx.x * 32 + threadIdx.x;
    int y0 = blockIdx.y * 32;
    #pragma unroll
    for (int k = 0; k < 4; k++) {
        int y = y0 + threadIdx.y + k * 8;
        tile[threadIdx.y + k * 8][threadIdx.x] = Ab[(size_t)y * NN + x];
    }
    __syncthreads();
    int x2 = y0 + threadIdx.x;
    int y20 = blockIdx.x * 32;
    #pragma unroll
    for (int k = 0; k < 4; k++) {
        int y2 = y20 + threadIdx.y + k * 8;
        ob[(size_t)y2 * NN + x2] = tile[threadIdx.x][threadIdx.y + k * 8];
    }
}

// ------------------------------------------------------------------
// Kernel 4: per-batch SGEMM  C[q][cl] = sum_n A[q][n] * Xt[n][cl]
// 128x128 tile, BK=16, 256 threads, 8x8 microtile, scattered epilogue
// into h_prime layout [b][c][q][l]
// ------------------------------------------------------------------
__global__ __launch_bounds__(256, 2) void gemm_kernel(float* __restrict__ out)
{
    __shared__ float As[16 * 132];   // [k][m], pitch 132
    __shared__ float Bs[16 * 128];   // [k][n]

    int b = blockIdx.z;
    int m0 = blockIdx.y * 128;       // q tile
    int n0 = blockIdx.x * 128;       // cl tile
    const float* Am = g_A  + (size_t)b * NN * NN;   // [q][n]
    const float* Bm = g_xt + (size_t)b * NN * CL;   // [n][cl]

    int tid = threadIdx.x;
    int tx = tid & 15, ty = tid >> 4;

    int arow = tid >> 2;             // 0..63
    int ak4  = (tid & 3) * 4;        // k offset 0,4,8,12
    int bk   = tid >> 5;             // 0..7
    int bc4  = (tid & 31) * 4;       // 0..124

    float acc[8][8] = {};
    float4 pa0, pa1, pb0, pb1;

    // prologue: tile 0
    pa0 = *(const float4*)&Am[(size_t)(m0 + arow) * NN + ak4];
    pa1 = *(const float4*)&Am[(size_t)(m0 + arow + 64) * NN + ak4];
    pb0 = *(const float4*)&Bm[(size_t)bk * CL + n0 + bc4];
    pb1 = *(const float4*)&Bm[(size_t)(bk + 8) * CL + n0 + bc4];
    As[(ak4 + 0) * 132 + arow] = pa0.x; As[(ak4 + 1) * 132 + arow] = pa0.y;
    As[(ak4 + 2) * 132 + arow] = pa0.z; As[(ak4 + 3) * 132 + arow] = pa0.w;
    As[(ak4 + 0) * 132 + arow + 64] = pa1.x; As[(ak4 + 1) * 132 + arow + 64] = pa1.y;
    As[(ak4 + 2) * 132 + arow + 64] = pa1.z; As[(ak4 + 3) * 132 + arow + 64] = pa1.w;
    *(float4*)&Bs[bk * 128 + bc4] = pb0;
    *(float4*)&Bs[(bk + 8) * 128 + bc4] = pb1;
    __syncthreads();

    const int T = NN / 16;           // 64
    for (int t = 0; t < T; t++) {
        if (t < T - 1) {
            int k0 = (t + 1) * 16;
            pa0 = *(const float4*)&Am[(size_t)(m0 + arow) * NN + k0 + ak4];
            pa1 = *(const float4*)&Am[(size_t)(m0 + arow + 64) * NN + k0 + ak4];
            pb0 = *(const float4*)&Bm[(size_t)(k0 + bk) * CL + n0 + bc4];
            pb1 = *(const float4*)&Bm[(size_t)(k0 + bk + 8) * CL + n0 + bc4];
        }
        #pragma unroll
        for (int kk = 0; kk < 16; kk++) {
            float4 a0 = *(float4*)&As[kk * 132 + ty * 4];
            float4 a1 = *(float4*)&As[kk * 132 + 64 + ty * 4];
            float4 b0v = *(float4*)&Bs[kk * 128 + tx * 4];
            float4 b1v = *(float4*)&Bs[kk * 128 + 64 + tx * 4];
            float av[8] = {a0.x, a0.y, a0.z, a0.w, a1.x, a1.y, a1.z, a1.w};
            float bv[8] = {b0v.x, b0v.y, b0v.z, b0v.w, b1v.x, b1v.y, b1v.z, b1v.w};
            #pragma unroll
            for (int i = 0; i < 8; i++)
                #pragma unroll
                for (int j = 0; j < 8; j++)
                    acc[i][j] += av[i] * bv[j];
        }
        __syncthreads();
        if (t < T - 1) {
            As[(ak4 + 0) * 132 + arow] = pa0.x; As[(ak4 + 1) * 132 + arow] = pa0.y;
            As[(ak4 + 2) * 132 + arow] = pa0.z; As[(ak4 + 3) * 132 + arow] = pa0.w;
            As[(ak4 + 0) * 132 + arow + 64] = pa1.x; As[(ak4 + 1) * 132 + arow + 64] = pa1.y;
            As[(ak4 + 2) * 132 + arow + 64] = pa1.z; As[(ak4 + 3) * 132 + arow + 64] = pa1.w;
            *(float4*)&Bs[bk * 128 + bc4] = pb0;
            *(float4*)&Bs[(bk + 8) * 128 + bc4] = pb1;
            __syncthreads();
        }
    }

    // epilogue: C[q][cl] -> h_prime[b][c][q][l], cl = c*12 + l
    float* ob = out + (size_t)b * COUT * NN * LL;
    #pragma unroll
    for (int i = 0; i < 8; i++) {
        int q = m0 + ((i < 4) ? (ty * 4 + i) : (64 + ty * 4 + i - 4));
        #pragma unroll
        for (int j = 0; j < 8; j++) {
            int cl = n0 + ((j < 4) ? (tx * 4 + j) : (64 + tx * 4 + j - 4));
            int c = cl / 12, l = cl - c * 12;
            ob[(size_t)c * (NN * LL) + q * 12 + l] = acc[i][j];
        }
    }
}

// ------------------------------------------------------------------
extern "C" void kernel_launch(void* const* d_in, const int* in_sizes, int n_in,
                              void* d_out, int out_size)
{
    const float* in  = (const float*)d_in[0];
    const float* adj = (const float*)d_in[1];
    const float* w0  = (const float*)d_in[2];
    const float* b0  = (const float*)d_in[3];
    const float* w1  = (const float*)d_in[4];

    float* out    = (float*)d_out;
    float* hprime = out;                                    // 16*64*1024*12
    float* att    = out + (size_t)BB * COUT * NN * LL;      // 16*1024*1024

    int convSmem = (192 * WPITCH + NT * PPITCH + 256) * (int)sizeof(float);
    cudaFuncSetAttribute(conv_kernel, cudaFuncAttributeMaxDynamicSharedMemorySize, convSmem);

    conv_kernel<<<BB * (NN / NT), 256, convSmem>>>(in, w0, b0, w1);
    softmax_kernel<<<BB * NN, 256>>>(adj);
    transpose_kernel<<<dim3(NN / 32, NN / 32, BB), dim3(32, 8)>>>(att);
    gemm_kernel<<<dim3(CL / 128, NN / 128, BB), 256>>>(hprime);
}

// round 7
// speedup vs baseline: 1.7810x; 1.7810x over previous
#include <cuda_runtime.h>
#include <cuda_bf16.h>
#include <cstdint>

#define BB   16
#define CIN  64
#define COUT 64
#define NN   1024
#define LL   12
#define CL   768   // COUT*LL

// ------------------- device scratch (allocation-free) -------------------
__device__ float g_A [(size_t)BB * NN * NN];   // softmax f32 (for attention output)
__device__ float g_f [(size_t)BB * NN];
__device__ __nv_bfloat16 g_Ahi[(size_t)BB * NN * NN];   // [b][q][n]   (GEMM A, K-contig)
__device__ __nv_bfloat16 g_Alo[(size_t)BB * NN * NN];
__device__ __nv_bfloat16 g_Xhi[(size_t)BB * CL * NN];   // [b][cl][n]  (GEMM B^T, K-contig)
__device__ __nv_bfloat16 g_Xlo[(size_t)BB * CL * NN];

// ------------------- PTX helpers (sm_80+ only; no tcgen05) -------------------
__device__ __forceinline__ uint32_t smem_u32(const void* p) {
    uint32_t a;
    asm("{ .reg .u64 t; cvta.to.shared.u64 t, %1; cvt.u32.u64 %0, t; }" : "=r"(a) : "l"(p));
    return a;
}
__device__ __forceinline__ void cp16(uint32_t dst, const void* src) {
    asm volatile("cp.async.cg.shared.global [%0], [%1], 16;" :: "r"(dst), "l"(src));
}
__device__ __forceinline__ void cp_commit() {
    asm volatile("cp.async.commit_group;" ::: "memory");
}
__device__ __forceinline__ void cp_wait1() {
    asm volatile("cp.async.wait_group 1;" ::: "memory");
}
__device__ __forceinline__ void ldsm4(uint32_t* r, uint32_t addr) {
    asm volatile("ldmatrix.sync.aligned.m8n8.x4.shared.b16 {%0,%1,%2,%3}, [%4];"
                 : "=r"(r[0]), "=r"(r[1]), "=r"(r[2]), "=r"(r[3]) : "r"(addr));
}
__device__ __forceinline__ void mma16816(float* d, const uint32_t* a, const uint32_t* bf) {
    asm volatile(
        "mma.sync.aligned.m16n8k16.row.col.f32.bf16.bf16.f32 "
        "{%0,%1,%2,%3}, {%4,%5,%6,%7}, {%8,%9}, {%0,%1,%2,%3};"
        : "+f"(d[0]), "+f"(d[1]), "+f"(d[2]), "+f"(d[3])
        : "r"(a[0]), "r"(a[1]), "r"(a[2]), "r"(a[3]), "r"(bf[0]), "r"(bf[1]));
}

// ------------------------------------------------------------------
// Kernel 1: conv0 (1x3, pad 1 on L) + bias; writes bf16 hi/lo X^T and f
// ------------------------------------------------------------------
#define NT 16
#define WPITCH 65
#define PPITCH 897   // 64*14 + 1

__global__ __launch_bounds__(256) void conv_kernel(
    const float* __restrict__ in, const float* __restrict__ w0,
    const float* __restrict__ b0, const float* __restrict__ w1)
{
    extern __shared__ float sm[];
    float* Wsh = sm;
    float* Psh = sm + 192 * WPITCH;
    float* red = Psh + NT * PPITCH;

    int blk = blockIdx.x;
    int b   = blk >> 6;
    int n0  = (blk & 63) * NT;
    int tid = threadIdx.x;

    for (int idx = tid; idx < COUT * 192; idx += 256) {
        int cout = idx / 192, r = idx % 192;
        Wsh[r * WPITCH + cout] = w0[idx];
    }
    for (int idx = tid; idx < NT * CIN * 2; idx += 256) {
        int nt = idx >> 7; int r = idx & 127; int cin = r >> 1; int side = r & 1;
        Psh[nt * PPITCH + cin * 14 + side * 13] = 0.f;
    }
    const float* inb = in + (size_t)b * CIN * NN * LL;
    for (int idx = tid; idx < NT * CIN * LL; idx += 256) {
        int cin = idx / (NT * LL); int r = idx % (NT * LL);
        int nt = r / LL; int l = r % LL;
        Psh[nt * PPITCH + cin * 14 + l + 1] = inb[((size_t)cin * NN + n0 + nt) * LL + l];
    }
    __syncthreads();

    int cg = tid >> 4, nt = tid & 15;
    float acc[4][12];
    #pragma unroll
    for (int u = 0; u < 4; u++) {
        float bv = b0[cg * 4 + u];
        #pragma unroll
        for (int l = 0; l < 12; l++) acc[u][l] = bv;
    }
    const float* prow = Psh + nt * PPITCH;
    for (int cin = 0; cin < CIN; cin++) {
        float pv[14];
        #pragma unroll
        for (int x = 0; x < 14; x++) pv[x] = prow[cin * 14 + x];
        #pragma unroll
        for (int kt = 0; kt < 3; kt++) {
            float wv[4];
            #pragma unroll
            for (int u = 0; u < 4; u++) wv[u] = Wsh[(cin * 3 + kt) * WPITCH + cg * 4 + u];
            #pragma unroll
            for (int u = 0; u < 4; u++)
                #pragma unroll
                for (int l = 0; l < 12; l++)
                    acc[u][l] += wv[u] * pv[l + kt];
        }
    }
    size_t xbase = (size_t)b * CL * NN;
    float fp = 0.f;
    #pragma unroll
    for (int u = 0; u < 4; u++) {
        int c = cg * 4 + u;
        #pragma unroll
        for (int l = 0; l < 12; l++) {
            float v = acc[u][l];
            int cl = c * 12 + l;
            __nv_bfloat16 h = __float2bfloat16(v);
            g_Xhi[xbase + (size_t)cl * NN + n0 + nt] = h;
            g_Xlo[xbase + (size_t)cl * NN + n0 + nt] = __float2bfloat16(v - __bfloat162float(h));
            fp += v * __ldg(&w1[cl]);
        }
    }
    red[nt * 16 + cg] = fp;
    __syncthreads();
    if (cg == 0) {
        float s = 0.f;
        #pragma unroll
        for (int k = 0; k < 16; k++) s += red[nt * 16 + k];
        g_f[b * NN + n0 + nt] = s;
    }
}

// ------------------------------------------------------------------
// Kernel 2: row softmax; writes f32 A + bf16 hi/lo A
// ------------------------------------------------------------------
__global__ __launch_bounds__(256) void softmax_kernel(const float* __restrict__ adj)
{
    int row = blockIdx.x;
    int b = row >> 10;
    int tid = threadIdx.x;
    const float* arow = adj + (size_t)row * NN;
    const float* fb = g_f + b * NN;
    float fi = fb[row & 1023];

    float zv[4]; float mx = -1e30f;
    #pragma unroll
    for (int k = 0; k < 4; k++) {
        int j = tid + k * 256;
        float lg = fi + fb[j];
        float z = (lg >= 0.f ? lg : 0.2f * lg) + arow[j];
        zv[k] = z; mx = fmaxf(mx, z);
    }
    __shared__ float sred[32];
    #pragma unroll
    for (int o = 16; o > 0; o >>= 1) mx = fmaxf(mx, __shfl_xor_sync(0xffffffffu, mx, o));
    if ((tid & 31) == 0) sred[tid >> 5] = mx;
    __syncthreads();
    if (tid < 32) {
        float v = (tid < 8) ? sred[tid] : -1e30f;
        #pragma unroll
        for (int o = 4; o > 0; o >>= 1) v = fmaxf(v, __shfl_xor_sync(0xffffffffu, v, o));
        if (tid == 0) sred[0] = v;
    }
    __syncthreads();
    mx = sred[0];
    __syncthreads();

    float ev[4]; float s = 0.f;
    #pragma unroll
    for (int k = 0; k < 4; k++) { ev[k] = __expf(zv[k] - mx); s += ev[k]; }
    #pragma unroll
    for (int o = 16; o > 0; o >>= 1) s += __shfl_xor_sync(0xffffffffu, s, o);
    if ((tid & 31) == 0) sred[tid >> 5] = s;
    __syncthreads();
    if (tid < 32) {
        float v = (tid < 8) ? sred[tid] : 0.f;
        #pragma unroll
        for (int o = 4; o > 0; o >>= 1) v += __shfl_xor_sync(0xffffffffu, v, o);
        if (tid == 0) sred[0] = v;
    }
    __syncthreads();
    float inv = 1.f / sred[0];

    float* Ar = g_A + (size_t)row * NN;
    size_t rb = (size_t)row * NN;
    #pragma unroll
    for (int k = 0; k < 4; k++) {
        int j = tid + k * 256;
        float p = ev[k] * inv;
        Ar[j] = p;
        __nv_bfloat16 h = __float2bfloat16(p);
        g_Ahi[rb + j] = h;
        g_Alo[rb + j] = __float2bfloat16(p - __bfloat162float(h));
    }
}

// ------------------------------------------------------------------
// Kernel 3: attention output = A^T per batch
// ------------------------------------------------------------------
__global__ void transpose_kernel(float* __restrict__ outAtt)
{
    __shared__ float tile[32][33];
    int b = blockIdx.z;
    const float* Ab = g_A + (size_t)b * NN * NN;
    float* ob = outAtt + (size_t)b * NN * NN;
    int x = blockIdx.x * 32 + threadIdx.x;
    int y0 = blockIdx.y * 32;
    #pragma unroll
    for (int k = 0; k < 4; k++) {
        int y = y0 + threadIdx.y + k * 8;
        tile[threadIdx.y + k * 8][threadIdx.x] = Ab[(size_t)y * NN + x];
    }
    __syncthreads();
    int x2 = y0 + threadIdx.x;
    int y20 = blockIdx.x * 32;
    #pragma unroll
    for (int k = 0; k < 4; k++) {
        int y2 = y20 + threadIdx.y + k * 8;
        ob[(size_t)y2 * NN + x2] = tile[threadIdx.x][threadIdx.y + k * 8];
    }
}

// ------------------------------------------------------------------
// Kernel 4: HMMA (mma.sync bf16) 3-term split GEMM
// C[q][cl] = sum_n A[q][n] * X[n][cl]
// CTA tile 128(m) x 128(n), K-chunk 32, 3-stage cp.async pipeline.
// smem tile rows: [row][ hi k0..31 | lo k0..31 ] = 128B, unit^(row&7) swizzle
// ------------------------------------------------------------------
#define STAGE_BYTES (32 * 1024)
#define XT_OFF      (16 * 1024)
#define NCHUNK      32

__device__ __forceinline__ void issue_stage(uint32_t sb,
    const __nv_bfloat16* Ah, const __nv_bfloat16* Al,
    const __nv_bfloat16* Xh, const __nv_bfloat16* Xl,
    int k0, int tid)
{
    int cm = tid >> 3;          // base row (0..31), handles rows cm+32r
    int cu = tid & 7;           // 16B unit within 128B row
    bool isHi = cu < 4;
    int kc = (isHi ? cu : cu - 4) * 8;   // k offset of this 16B chunk
    #pragma unroll
    for (int r = 0; r < 4; r++) {
        int m = cm + 32 * r;
        uint32_t sw = (uint32_t)((cu ^ (m & 7)) << 4);
        const __nv_bfloat16* srcA = (isHi ? Ah : Al) + (size_t)m * NN + k0 + kc;
        const __nv_bfloat16* srcX = (isHi ? Xh : Xl) + (size_t)m * NN + k0 + kc;
        cp16(sb + m * 128 + sw, srcA);
        cp16(sb + XT_OFF + m * 128 + sw, srcX);
    }
}

__global__ __launch_bounds__(256) void gemm_hmma_kernel(float* __restrict__ out)
{
    extern __shared__ char smc[];
    int tid  = threadIdx.x;
    int lane = tid & 31, w = tid >> 5;
    int b  = blockIdx.z;
    int n0 = blockIdx.x * 128;   // cl tile (0..640; CL/128 = 6 tiles)
    int m0 = blockIdx.y * 128;   // q tile

    const __nv_bfloat16* Ah = g_Ahi + ((size_t)(b * NN + m0)) * NN;
    const __nv_bfloat16* Al = g_Alo + ((size_t)(b * NN + m0)) * NN;
    const __nv_bfloat16* Xh = g_Xhi + ((size_t)(b * CL + n0)) * NN;
    const __nv_bfloat16* Xl = g_Xlo + ((size_t)(b * CL + n0)) * NN;

    uint32_t smb = smem_u32(smc);

    // prologue: stages 0,1
    issue_stage(smb, Ah, Al, Xh, Xl, 0, tid);
    cp_commit();
    issue_stage(smb + STAGE_BYTES, Ah, Al, Xh, Xl, 32, tid);
    cp_commit();

    int wm = (w & 3) * 32;       // warp m offset in tile
    int wn = (w >> 2) * 64;      // warp n offset

    float acc[2][8][4];
    #pragma unroll
    for (int t = 0; t < 2; t++)
        #pragma unroll
        for (int bk = 0; bk < 8; bk++)
            #pragma unroll
            for (int e = 0; e < 4; e++) acc[t][bk][e] = 0.f;

    // ldmatrix lane coords (constant across stages)
    int ai  = lane & 15, ahf = lane >> 4;                  // A: row i, k-half
    int xcb = (lane >> 4) & 1, xkh = (lane >> 3) & 1, xc7 = lane & 7;  // X

    for (int t = 0; t < NCHUNK; t++) {
        cp_wait1();
        __syncthreads();
        if (t + 2 < NCHUNK)
            issue_stage(smb + ((t + 2) % 3) * STAGE_BYTES, Ah, Al, Xh, Xl, (t + 2) * 32, tid);
        cp_commit();

        uint32_t sa = smb + (t % 3) * STAGE_BYTES;
        uint32_t sx = sa + XT_OFF;

        #pragma unroll
        for (int s = 0; s < 2; s++) {       // two k16 steps per chunk
            uint32_t ah[2][4], al[2][4];
            #pragma unroll
            for (int mt = 0; mt < 2; mt++) {
                int row = wm + mt * 16 + ai;
                int cuH = 2 * s + ahf;
                ldsm4(ah[mt], sa + row * 128 + ((cuH ^ (row & 7)) << 4));
                ldsm4(al[mt], sa + row * 128 + (((cuH + 4) ^ (row & 7)) << 4));
            }
            uint32_t xh[4][4], xl[4][4];
            #pragma unroll
            for (int g = 0; g < 4; g++) {
                int col = wn + g * 16 + xcb * 8 + xc7;
                int cuH = 2 * s + xkh;
                ldsm4(xh[g], sx + col * 128 + ((cuH ^ (col & 7)) << 4));
                ldsm4(xl[g], sx + col * 128 + (((cuH + 4) ^ (col & 7)) << 4));
            }
            #pragma unroll
            for (int mt = 0; mt < 2; mt++)
                #pragma unroll
                for (int g = 0; g < 4; g++) {
                    mma16816(acc[mt][2 * g],     ah[mt], &xh[g][0]);
                    mma16816(acc[mt][2 * g],     al[mt], &xh[g][0]);
                    mma16816(acc[mt][2 * g],     ah[mt], &xl[g][0]);
                    mma16816(acc[mt][2 * g + 1], ah[mt], &xh[g][2]);
                    mma16816(acc[mt][2 * g + 1], al[mt], &xh[g][2]);
                    mma16816(acc[mt][2 * g + 1], ah[mt], &xl[g][2]);
                }
        }
        __syncthreads();
    }

    // epilogue: C[q][cl] -> out[b][c][q][l], cl = c*12 + l
    float* ob = out + (size_t)b * COUT * NN * LL;
    int g8 = lane >> 2, t4 = lane & 3;
    #pragma unroll
    for (int mt = 0; mt < 2; mt++) {
        int q0 = m0 + wm + mt * 16 + g8;
        #pragma unroll
        for (int bk = 0; bk < 8; bk++) {
            int cl0 = n0 + wn + bk * 8 + t4 * 2;
            #pragma unroll
            for (int e = 0; e < 4; e++) {
                int q  = q0 + (e >> 1) * 8;
                int cl = cl0 + (e & 1);
                int c = cl / 12, l = cl - c * 12;
                ob[(size_t)c * (NN * LL) + q * 12 + l] = acc[mt][bk][e];
            }
        }
    }
}

// ------------------------------------------------------------------
extern "C" void kernel_launch(void* const* d_in, const int* in_sizes, int n_in,
                              void* d_out, int out_size)
{
    const float* in  = (const float*)d_in[0];
    const float* adj = (const float*)d_in[1];
    const float* w0  = (const float*)d_in[2];
    const float* b0  = (const float*)d_in[3];
    const float* w1  = (const float*)d_in[4];

    float* out    = (float*)d_out;
    float* hprime = out;
    float* att    = out + (size_t)BB * COUT * NN * LL;

    int convSmem = (192 * WPITCH + NT * PPITCH + 256) * (int)sizeof(float);
    cudaFuncSetAttribute(conv_kernel, cudaFuncAttributeMaxDynamicSharedMemorySize, convSmem);
    cudaFuncSetAttribute(gemm_hmma_kernel, cudaFuncAttributeMaxDynamicSharedMemorySize, 3 * STAGE_BYTES);

    conv_kernel<<<BB * (NN / NT), 256, convSmem>>>(in, w0, b0, w1);
    softmax_kernel<<<BB * NN, 256>>>(adj);
    transpose_kernel<<<dim3(NN / 32, NN / 32, BB), dim3(32, 8)>>>(att);
    gemm_hmma_kernel<<<dim3(CL / 128, NN / 128, BB), 256, 3 * STAGE_BYTES>>>(hprime);
}

// round 8
// speedup vs baseline: 1.9314x; 1.0845x over previous
#include <cuda_runtime.h>
#include <cuda_bf16.h>
#include <cstdint>

#define BB   16
#define CIN  64
#define COUT 64
#define NN   1024
#define LL   12
#define CL   768   // COUT*LL

// ------------------- device scratch (allocation-free) -------------------
__device__ float g_f  [(size_t)BB * NN];
__device__ float g_mx [(size_t)BB * NN];
__device__ float g_si [(size_t)BB * NN];
__device__ __nv_bfloat16 g_Ahi[(size_t)BB * NN * NN];   // [b][q][n]   (GEMM A, K-contig)
__device__ __nv_bfloat16 g_Alo[(size_t)BB * NN * NN];
__device__ __nv_bfloat16 g_Xhi[(size_t)BB * CL * NN];   // [b][cl][n]  (GEMM B^T, K-contig)
__device__ __nv_bfloat16 g_Xlo[(size_t)BB * CL * NN];

// ------------------- PTX helpers (sm_80+ only; no tcgen05) -------------------
__device__ __forceinline__ uint32_t smem_u32(const void* p) {
    uint32_t a;
    asm("{ .reg .u64 t; cvta.to.shared.u64 t, %1; cvt.u32.u64 %0, t; }" : "=r"(a) : "l"(p));
    return a;
}
__device__ __forceinline__ void cp16(uint32_t dst, const void* src) {
    asm volatile("cp.async.cg.shared.global [%0], [%1], 16;" :: "r"(dst), "l"(src));
}
__device__ __forceinline__ void cp_commit() {
    asm volatile("cp.async.commit_group;" ::: "memory");
}
__device__ __forceinline__ void cp_wait1() {
    asm volatile("cp.async.wait_group 1;" ::: "memory");
}
__device__ __forceinline__ void ldsm4(uint32_t* r, uint32_t addr) {
    asm volatile("ldmatrix.sync.aligned.m8n8.x4.shared.b16 {%0,%1,%2,%3}, [%4];"
                 : "=r"(r[0]), "=r"(r[1]), "=r"(r[2]), "=r"(r[3]) : "r"(addr));
}
__device__ __forceinline__ void mma16816(float* d, const uint32_t* a, const uint32_t* bf) {
    asm volatile(
        "mma.sync.aligned.m16n8k16.row.col.f32.bf16.bf16.f32 "
        "{%0,%1,%2,%3}, {%4,%5,%6,%7}, {%8,%9}, {%0,%1,%2,%3};"
        : "+f"(d[0]), "+f"(d[1]), "+f"(d[2]), "+f"(d[3])
        : "r"(a[0]), "r"(a[1]), "r"(a[2]), "r"(a[3]), "r"(bf[0]), "r"(bf[1]));
}

// ------------------------------------------------------------------
// Kernel 1: conv0 (1x3, pad 1 on L) + bias; writes bf16 hi/lo X^T and f
// ------------------------------------------------------------------
#define NT 16
#define WPITCH 65
#define PPITCH 897   // 64*14 + 1

__global__ __launch_bounds__(256) void conv_kernel(
    const float* __restrict__ in, const float* __restrict__ w0,
    const float* __restrict__ b0, const float* __restrict__ w1)
{
    extern __shared__ float sm[];
    float* Wsh = sm;
    float* Psh = sm + 192 * WPITCH;
    float* red = Psh + NT * PPITCH;

    int blk = blockIdx.x;
    int b   = blk >> 6;
    int n0  = (blk & 63) * NT;
    int tid = threadIdx.x;

    for (int idx = tid; idx < COUT * 192; idx += 256) {
        int cout = idx / 192, r = idx % 192;
        Wsh[r * WPITCH + cout] = w0[idx];
    }
    for (int idx = tid; idx < NT * CIN * 2; idx += 256) {
        int nt = idx >> 7; int r = idx & 127; int cin = r >> 1; int side = r & 1;
        Psh[nt * PPITCH + cin * 14 + side * 13] = 0.f;
    }
    const float* inb = in + (size_t)b * CIN * NN * LL;
    for (int idx = tid; idx < NT * CIN * LL; idx += 256) {
        int cin = idx / (NT * LL); int r = idx % (NT * LL);
        int nt = r / LL; int l = r % LL;
        Psh[nt * PPITCH + cin * 14 + l + 1] = inb[((size_t)cin * NN + n0 + nt) * LL + l];
    }
    __syncthreads();

    int cg = tid >> 4, nt = tid & 15;
    float acc[4][12];
    #pragma unroll
    for (int u = 0; u < 4; u++) {
        float bv = b0[cg * 4 + u];
        #pragma unroll
        for (int l = 0; l < 12; l++) acc[u][l] = bv;
    }
    const float* prow = Psh + nt * PPITCH;
    for (int cin = 0; cin < CIN; cin++) {
        float pv[14];
        #pragma unroll
        for (int x = 0; x < 14; x++) pv[x] = prow[cin * 14 + x];
        #pragma unroll
        for (int kt = 0; kt < 3; kt++) {
            float wv[4];
            #pragma unroll
            for (int u = 0; u < 4; u++) wv[u] = Wsh[(cin * 3 + kt) * WPITCH + cg * 4 + u];
            #pragma unroll
            for (int u = 0; u < 4; u++)
                #pragma unroll
                for (int l = 0; l < 12; l++)
                    acc[u][l] += wv[u] * pv[l + kt];
        }
    }
    size_t xbase = (size_t)b * CL * NN;
    float fp = 0.f;
    #pragma unroll
    for (int u = 0; u < 4; u++) {
        int c = cg * 4 + u;
        #pragma unroll
        for (int l = 0; l < 12; l++) {
            float v = acc[u][l];
            int cl = c * 12 + l;
            __nv_bfloat16 h = __float2bfloat16(v);
            g_Xhi[xbase + (size_t)cl * NN + n0 + nt] = h;
            g_Xlo[xbase + (size_t)cl * NN + n0 + nt] = __float2bfloat16(v - __bfloat162float(h));
            fp += v * __ldg(&w1[cl]);
        }
    }
    red[nt * 16 + cg] = fp;
    __syncthreads();
    if (cg == 0) {
        float s = 0.f;
        #pragma unroll
        for (int k = 0; k < 16; k++) s += red[nt * 16 + k];
        g_f[b * NN + n0 + nt] = s;
    }
}

// ------------------------------------------------------------------
// Kernel 2a: row stats (max, inverse sum) of z = leaky(f_i+f_j)+adj
// ------------------------------------------------------------------
__global__ __launch_bounds__(256) void stats_kernel(const float* __restrict__ adj)
{
    int row = blockIdx.x;
    int b = row >> 10;
    int tid = threadIdx.x;
    const float* arow = adj + (size_t)row * NN;
    const float* fb = g_f + b * NN;
    float fi = fb[row & 1023];

    float zv[4]; float mx = -1e30f;
    #pragma unroll
    for (int k = 0; k < 4; k++) {
        int j = tid + k * 256;
        float lg = fi + fb[j];
        float z = (lg >= 0.f ? lg : 0.2f * lg) + arow[j];
        zv[k] = z; mx = fmaxf(mx, z);
    }
    __shared__ float sred[32];
    #pragma unroll
    for (int o = 16; o > 0; o >>= 1) mx = fmaxf(mx, __shfl_xor_sync(0xffffffffu, mx, o));
    if ((tid & 31) == 0) sred[tid >> 5] = mx;
    __syncthreads();
    if (tid < 32) {
        float v = (tid < 8) ? sred[tid] : -1e30f;
        #pragma unroll
        for (int o = 4; o > 0; o >>= 1) v = fmaxf(v, __shfl_xor_sync(0xffffffffu, v, o));
        if (tid == 0) sred[0] = v;
    }
    __syncthreads();
    mx = sred[0];
    __syncthreads();

    float s = 0.f;
    #pragma unroll
    for (int k = 0; k < 4; k++) s += __expf(zv[k] - mx);
    #pragma unroll
    for (int o = 16; o > 0; o >>= 1) s += __shfl_xor_sync(0xffffffffu, s, o);
    if ((tid & 31) == 0) sred[tid >> 5] = s;
    __syncthreads();
    if (tid < 32) {
        float v = (tid < 8) ? sred[tid] : 0.f;
        #pragma unroll
        for (int o = 4; o > 0; o >>= 1) v += __shfl_xor_sync(0xffffffffu, v, o);
        if (tid == 0) { g_mx[row] = mx; g_si[row] = 1.f / v; }
    }
}

// ------------------------------------------------------------------
// Kernel 2b: emit P tiles: bf16 hi/lo [i][j] + f32 attention output [j][i]
// 32x32 tile per block (256 threads, 4 elems each)
// ------------------------------------------------------------------
__global__ __launch_bounds__(256) void emit_kernel(
    const float* __restrict__ adj, float* __restrict__ outAtt)
{
    __shared__ float pt[32][33];
    int b  = blockIdx.z;
    int i0 = blockIdx.y * 32;
    int j0 = blockIdx.x * 32;
    int tid = threadIdx.x;
    int ii = tid >> 3, jt = tid & 7;

    const float* fb = g_f + b * NN;
    int irow = (b << 10) + i0 + ii;
    float fi = fb[i0 + ii];
    float mx = g_mx[irow];
    float si = g_si[irow];

    float4 av = *(const float4*)&adj[((size_t)irow) * NN + j0 + jt * 4];
    float p[4];
    #pragma unroll
    for (int e = 0; e < 4; e++) {
        int j = j0 + jt * 4 + e;
        float lg = fi + fb[j];
        float z = (lg >= 0.f ? lg : 0.2f * lg) + ((const float*)&av)[e];
        p[e] = __expf(z - mx) * si;
        pt[ii][jt * 4 + e] = p[e];
    }
    // bf16 hi/lo, coalesced along j
    size_t rb = ((size_t)irow) * NN + j0 + jt * 4;
    uint2 hv, lv;
    __nv_bfloat16 h0 = __float2bfloat16(p[0]), h1 = __float2bfloat16(p[1]);
    __nv_bfloat16 h2 = __float2bfloat16(p[2]), h3 = __float2bfloat16(p[3]);
    hv.x = ((uint32_t)*(uint16_t*)&h1 << 16) | *(uint16_t*)&h0;
    hv.y = ((uint32_t)*(uint16_t*)&h3 << 16) | *(uint16_t*)&h2;
    __nv_bfloat16 l0 = __float2bfloat16(p[0] - __bfloat162float(h0));
    __nv_bfloat16 l1 = __float2bfloat16(p[1] - __bfloat162float(h1));
    __nv_bfloat16 l2 = __float2bfloat16(p[2] - __bfloat162float(h2));
    __nv_bfloat16 l3 = __float2bfloat16(p[3] - __bfloat162float(h3));
    lv.x = ((uint32_t)*(uint16_t*)&l1 << 16) | *(uint16_t*)&l0;
    lv.y = ((uint32_t)*(uint16_t*)&l3 << 16) | *(uint16_t*)&l2;
    *(uint2*)&g_Ahi[rb] = hv;
    *(uint2*)&g_Alo[rb] = lv;

    __syncthreads();
    // transposed f32 write: att[b][j][i]
    int jj = tid >> 3, it = tid & 7;
    float4 ov;
    ov.x = pt[it * 4 + 0][jj];
    ov.y = pt[it * 4 + 1][jj];
    ov.z = pt[it * 4 + 2][jj];
    ov.w = pt[it * 4 + 3][jj];
    *(float4*)&outAtt[(((size_t)(b << 10) + j0 + jj)) * NN + i0 + it * 4] = ov;
}

// ------------------------------------------------------------------
// Kernel 3: HMMA (mma.sync bf16) 3-term split GEMM, 2 CTAs/SM
// C[q][cl] = sum_n A[q][n] * X[n][cl]
// CTA tile 128(m) x 128(n), K-chunk 32, 3-stage cp.async pipeline.
// smem tile rows: [row][ hi k0..31 | lo k0..31 ] = 128B, unit^(row&7) swizzle
// ------------------------------------------------------------------
#define STAGE_BYTES (32 * 1024)
#define XT_OFF      (16 * 1024)
#define NCHUNK      32

__device__ __forceinline__ void issue_stage(uint32_t sb,
    const __nv_bfloat16* Ah, const __nv_bfloat16* Al,
    const __nv_bfloat16* Xh, const __nv_bfloat16* Xl,
    int k0, int tid)
{
    int cm = tid >> 3;          // base row (0..31), handles rows cm+32r
    int cu = tid & 7;           // 16B unit within 128B row
    bool isHi = cu < 4;
    int kc = (isHi ? cu : cu - 4) * 8;   // k offset of this 16B chunk
    #pragma unroll
    for (int r = 0; r < 4; r++) {
        int m = cm + 32 * r;
        uint32_t sw = (uint32_t)((cu ^ (m & 7)) << 4);
        const __nv_bfloat16* srcA = (isHi ? Ah : Al) + (size_t)m * NN + k0 + kc;
        const __nv_bfloat16* srcX = (isHi ? Xh : Xl) + (size_t)m * NN + k0 + kc;
        cp16(sb + m * 128 + sw, srcA);
        cp16(sb + XT_OFF + m * 128 + sw, srcX);
    }
}

__global__ __launch_bounds__(256, 2) void gemm_hmma_kernel(float* __restrict__ out)
{
    extern __shared__ char smc[];
    int tid  = threadIdx.x;
    int lane = tid & 31, w = tid >> 5;
    int b  = blockIdx.z;
    int n0 = blockIdx.x * 128;   // cl tile (CL/128 = 6 tiles)
    int m0 = blockIdx.y * 128;   // q tile

    const __nv_bfloat16* Ah = g_Ahi + ((size_t)(b * NN + m0)) * NN;
    const __nv_bfloat16* Al = g_Alo + ((size_t)(b * NN + m0)) * NN;
    const __nv_bfloat16* Xh = g_Xhi + ((size_t)(b * CL + n0)) * NN;
    const __nv_bfloat16* Xl = g_Xlo + ((size_t)(b * CL + n0)) * NN;

    uint32_t smb = smem_u32(smc);

    // prologue: stages 0,1
    issue_stage(smb, Ah, Al, Xh, Xl, 0, tid);
    cp_commit();
    issue_stage(smb + STAGE_BYTES, Ah, Al, Xh, Xl, 32, tid);
    cp_commit();

    int wm = (w & 3) * 32;       // warp m offset in tile
    int wn = (w >> 2) * 64;      // warp n offset

    float acc[2][8][4];
    #pragma unroll
    for (int t = 0; t < 2; t++)
        #pragma unroll
        for (int bk = 0; bk < 8; bk++)
            #pragma unroll
            for (int e = 0; e < 4; e++) acc[t][bk][e] = 0.f;

    // ldmatrix lane coords (constant across stages)
    int ai  = lane & 15, ahf = lane >> 4;                  // A: row i, k-half
    int xcb = (lane >> 4) & 1, xkh = (lane >> 3) & 1, xc7 = lane & 7;  // X

    for (int t = 0; t < NCHUNK; t++) {
        cp_wait1();
        __syncthreads();
        if (t + 2 < NCHUNK)
            issue_stage(smb + ((t + 2) % 3) * STAGE_BYTES, Ah, Al, Xh, Xl, (t + 2) * 32, tid);
        cp_commit();

        uint32_t sa = smb + (t % 3) * STAGE_BYTES;
        uint32_t sx = sa + XT_OFF;

        #pragma unroll
        for (int s = 0; s < 2; s++) {       // two k16 steps per chunk
            uint32_t ah[2][4], al[2][4];
            #pragma unroll
            for (int mt = 0; mt < 2; mt++) {
                int row = wm + mt * 16 + ai;
                int cuH = 2 * s + ahf;
                ldsm4(ah[mt], sa + row * 128 + ((cuH ^ (row & 7)) << 4));
                ldsm4(al[mt], sa + row * 128 + (((cuH + 4) ^ (row & 7)) << 4));
            }
            #pragma unroll
            for (int g = 0; g < 4; g++) {   // X groups loaded per-iteration (reg pressure)
                uint32_t xh[4], xl[4];
                int col = wn + g * 16 + xcb * 8 + xc7;
                int cuH = 2 * s + xkh;
                ldsm4(xh, sx + col * 128 + ((cuH ^ (col & 7)) << 4));
                ldsm4(xl, sx + col * 128 + (((cuH + 4) ^ (col & 7)) << 4));
                #pragma unroll
                for (int mt = 0; mt < 2; mt++) {
                    mma16816(acc[mt][2 * g],     ah[mt], &xh[0]);
                    mma16816(acc[mt][2 * g],     al[mt], &xh[0]);
                    mma16816(acc[mt][2 * g],     ah[mt], &xl[0]);
                    mma16816(acc[mt][2 * g + 1], ah[mt], &xh[2]);
                    mma16816(acc[mt][2 * g + 1], al[mt], &xh[2]);
                    mma16816(acc[mt][2 * g + 1], ah[mt], &xl[2]);
                }
            }
        }
        __syncthreads();
    }

    // epilogue: C[q][cl] -> out[b][c][q][l], cl = c*12 + l
    float* ob = out + (size_t)b * COUT * NN * LL;
    int g8 = lane >> 2, t4 = lane & 3;
    #pragma unroll
    for (int mt = 0; mt < 2; mt++) {
        int q0 = m0 + wm + mt * 16 + g8;
        #pragma unroll
        for (int bk = 0; bk < 8; bk++) {
            int cl0 = n0 + wn + bk * 8 + t4 * 2;
            #pragma unroll
            for (int e = 0; e < 4; e++) {
                int q  = q0 + (e >> 1) * 8;
                int cl = cl0 + (e & 1);
                int c = cl / 12, l = cl - c * 12;
                ob[(size_t)c * (NN * LL) + q * 12 + l] = acc[mt][bk][e];
            }
        }
    }
}

// ------------------------------------------------------------------
extern "C" void kernel_launch(void* const* d_in, const int* in_sizes, int n_in,
                              void* d_out, int out_size)
{
    const float* in  = (const float*)d_in[0];
    const float* adj = (const float*)d_in[1];
    const float* w0  = (const float*)d_in[2];
    const float* b0  = (const float*)d_in[3];
    const float* w1  = (const float*)d_in[4];

    float* out    = (float*)d_out;
    float* hprime = out;
    float* att    = out + (size_t)BB * COUT * NN * LL;

    int convSmem = (192 * WPITCH + NT * PPITCH + 256) * (int)sizeof(float);
    cudaFuncSetAttribute(conv_kernel, cudaFuncAttributeMaxDynamicSharedMemorySize, convSmem);
    cudaFuncSetAttribute(gemm_hmma_kernel, cudaFuncAttributeMaxDynamicSharedMemorySize, 3 * STAGE_BYTES);

    conv_kernel<<<BB * (NN / NT), 256, convSmem>>>(in, w0, b0, w1);
    stats_kernel<<<BB * NN, 256>>>(adj);
    emit_kernel<<<dim3(NN / 32, NN / 32, BB), 256>>>(adj, att);
    gemm_hmma_kernel<<<dim3(CL / 128, NN / 128, BB), 256, 3 * STAGE_BYTES>>>(hprime);
}